// round 16
// baseline (speedup 1.0000x reference)
#include <cuda_runtime.h>
#include <cuda_fp16.h>
#include <cstdint>
#include <math.h>

// ---------------- problem constants ------------------------------------------
#define T_TOK 4096
#define D_DIM 1024
#define H_DIM 2816
#define E_NUM 8
#define CAP   4096

#define BM 128
#define BN 128
#define BK 32                      // K halves per stage: 64B data/row
#define RSB 80                     // padded smem row stride in BYTES
#define ATILE_B (BM * RSB)         // 10240 bytes per 128-row tile
#define NK1 (D_DIM / BK)           // 32
#define NK2 (H_DIM / BK)           // 88
#define NSTG1 6                    // ffn1 ring depth (preload 4)
#define NSTG2 5                    // ffn2 ring depth (preload 3, occ 2)
#define NB1  (H_DIM / BN)          // 22 n-blocks in ffn1; blockIdx.y==NB1 -> W3 conv

#define STG1_B (3 * ATILE_B)                   // A + B1 + B2 = 30720
#define STG2_B (2 * ATILE_B)                   // A + B = 20480
#define SMEM1_BYTES (NSTG1 * STG1_B)           // 184320
#define SMEM2_BYTES (NSTG2 * STG2_B)           // 102400

#define N4W ((long)E_NUM * H_DIM * D_DIM / 4)  // 5767168 float4 per weight tensor
#define N4O ((long)T_TOK * D_DIM / 4)          // 1048576 float4 in out

#define GATE_BLKS 512                          // 8 tokens per 256-thread block
#define ZERO_BLKS 128                          // out-zero blocks in K1
#define CONV12_BLKS 2048                       // W1+W2 converter blocks in K1
#define CONV3_BLKS 256                         // W3 converter blocks in K2 (y==NB1)

// ---------------- static device scratch --------------------------------------
__device__ __half g_xch[(size_t)T_TOK * D_DIM];
__device__ __half g_W1h[(size_t)E_NUM * H_DIM * D_DIM];
__device__ __half g_W2h[(size_t)E_NUM * H_DIM * D_DIM];
__device__ __half g_W3h[(size_t)E_NUM * D_DIM * H_DIM];
__device__ __half g_Hh [(size_t)E_NUM * CAP * H_DIM];
__device__ int    g_tok[E_NUM * CAP];
__device__ float  g_wgt[E_NUM * CAP];
__device__ int    g_cnt[E_NUM];

// ---------------- helpers -----------------------------------------------------
__device__ __forceinline__ uint32_t s2u(const void* p) {
    uint32_t a;
    asm("{ .reg .u64 t; cvta.to.shared.u64 t, %1; cvt.u32.u64 %0, t; }" : "=r"(a) : "l"(p));
    return a;
}

#define CPA16(s, g) asm volatile("cp.async.cg.shared.global [%0], [%1], 16;" :: "r"(s), "l"(g))
#define CPA_COMMIT() asm volatile("cp.async.commit_group;" ::: "memory")
#define CPA_WAIT(n)  asm volatile("cp.async.wait_group %0;" :: "n"(n) : "memory")

#define LDSM_X4(r, addr)                                                          \
    asm volatile("ldmatrix.sync.aligned.m8n8.x4.shared.b16 {%0,%1,%2,%3}, [%4];"  \
        : "=r"((r)[0]), "=r"((r)[1]), "=r"((r)[2]), "=r"((r)[3]) : "r"(addr))

#define MMA_F16(d, a, b)                                                          \
    asm volatile(                                                                 \
        "mma.sync.aligned.m16n8k16.row.col.f32.f16.f16.f32 "                      \
        "{%0,%1,%2,%3},{%4,%5,%6,%7},{%8,%9},{%0,%1,%2,%3};"                      \
        : "+f"((d)[0]), "+f"((d)[1]), "+f"((d)[2]), "+f"((d)[3])                  \
        : "r"((a)[0]), "r"((a)[1]), "r"((a)[2]), "r"((a)[3]),                     \
          "r"((b)[0]), "r"((b)[1]))

__device__ __forceinline__ void conv_f4(const float4* __restrict__ s,
                                        __half2* __restrict__ d, long i) {
    float4 v = s[i];
    d[i * 2 + 0] = __floats2half2_rn(v.x, v.y);
    d[i * 2 + 1] = __floats2half2_rn(v.z, v.w);
}

// ---------------- K1: gate (+x conv) | out-zero | W1/W2 conversion -----------
__global__ void k_front(const float* __restrict__ x,
                        const float* __restrict__ Wg,
                        const float4* __restrict__ W1,
                        const float4* __restrict__ W2,
                        __half2* __restrict__ w1c,
                        __half2* __restrict__ w2c,
                        float4* __restrict__ out4) {
    if (blockIdx.x < GATE_BLKS) {
        // ---- gate: one warp per token; also writes fp16 x row ----
        int t = blockIdx.x * 8 + (threadIdx.x >> 5);
        int lane = threadIdx.x & 31;
        const float4* xr = (const float4*)(x + (size_t)t * D_DIM);
        float acc[E_NUM];
#pragma unroll
        for (int e = 0; e < E_NUM; e++) acc[e] = 0.f;
        for (int i = lane; i < D_DIM / 4; i += 32) {
            float4 xv = xr[i];
            uint2 u;
            __half2 h0 = __floats2half2_rn(xv.x, xv.y);
            __half2 h1 = __floats2half2_rn(xv.z, xv.w);
            u.x = *(uint32_t*)&h0; u.y = *(uint32_t*)&h1;
            *(uint2*)&g_xch[(size_t)t * D_DIM + i * 4] = u;
#pragma unroll
            for (int e = 0; e < E_NUM; e++) {
                float4 wv = ((const float4*)(Wg + (size_t)e * D_DIM))[i];
                acc[e] += xv.x * wv.x + xv.y * wv.y + xv.z * wv.z + xv.w * wv.w;
            }
        }
#pragma unroll
        for (int e = 0; e < E_NUM; e++)
#pragma unroll
            for (int o = 16; o > 0; o >>= 1)
                acc[e] += __shfl_xor_sync(0xffffffffu, acc[e], o);
        if (lane == 0) {
            int e0 = 0; float v0 = acc[0];
#pragma unroll
            for (int e = 1; e < E_NUM; e++) if (acc[e] > v0) { v0 = acc[e]; e0 = e; }
            int e1 = -1; float v1 = -INFINITY;
#pragma unroll
            for (int e = 0; e < E_NUM; e++)
                if (e != e0 && acc[e] > v1) { v1 = acc[e]; e1 = e; }
            int i0 = atomicAdd(&g_cnt[e0], 1);
            g_tok[e0 * CAP + i0] = t; g_wgt[e0 * CAP + i0] = v0;
            int i1 = atomicAdd(&g_cnt[e1], 1);
            g_tok[e1 * CAP + i1] = t; g_wgt[e1 * CAP + i1] = v1;
        }
    } else if (blockIdx.x < GATE_BLKS + ZERO_BLKS) {
        // ---- zero the fp32 output accumulator ----
        float4 z; z.x = 0.f; z.y = 0.f; z.z = 0.f; z.w = 0.f;
        const long stride = (long)ZERO_BLKS * 256;
        for (long i = (long)(blockIdx.x - GATE_BLKS) * 256 + threadIdx.x;
             i < N4O; i += stride)
            out4[i] = z;
    } else {
        // ---- W1 + W2 fp32->fp16 conversion, MLP=4 block-strided ----
        const long total = 2 * N4W;
        const long stride = (long)CONV12_BLKS * 1024;
        long base = (long)(blockIdx.x - GATE_BLKS - ZERO_BLKS) * 1024 + threadIdx.x;
        for (long i = base; i < total; i += stride) {
            float4 v[4];
            long j[4];
            int nv = 0;
#pragma unroll
            for (int u = 0; u < 4; u++) {
                long idx = i + (long)u * 256;
                if (idx < total) {
                    j[nv] = idx;
                    v[nv] = (idx < N4W) ? W1[idx] : W2[idx - N4W];
                    nv++;
                }
            }
#pragma unroll
            for (int u = 0; u < 4; u++) {
                if (u < nv) {
                    long idx = j[u];
                    __half2* d = (idx < N4W) ? w1c : w2c;
                    long off = (idx < N4W) ? idx : idx - N4W;
                    d[off * 2 + 0] = __floats2half2_rn(v[u].x, v[u].y);
                    d[off * 2 + 1] = __floats2half2_rn(v[u].z, v[u].w);
                }
            }
        }
    }
}

// ---------------- K2: GEMM1 (+W3 conversion blocks at y==NB1) ----------------
// Split-role: 512 threads = 8 positions (64x32 subtile) x 2 roles (gate/up).
// 6-stage cp.async ring, preload 4, barrier per 2 stages.
__global__ __launch_bounds__(512, 1)
void k_ffn1(const float4* __restrict__ W3, __half2* __restrict__ w3c) {
    if (blockIdx.y == NB1) {
        const long stride = (long)CONV3_BLKS * 512;
        for (long i = (long)blockIdx.x * 512 + threadIdx.x; i < N4W; i += stride)
            conv_f4(W3, w3c, i);
        return;
    }
    int e  = blockIdx.x >> 5;
    int m0 = (blockIdx.x & 31) * BM;
    int cnt = g_cnt[e];
    if (m0 >= cnt) return;
    int n0 = blockIdx.y * BN;

    extern __shared__ char sm[];

    int tid  = threadIdx.x;
    int wid  = tid >> 5, lane = tid & 31;
    int pos  = wid >> 1;
    int role = wid & 1;                // 0 = gate (W1), 1 = up (W2)
    int wm0  = (pos & 1) * 64;
    int wn0  = (pos >> 1) * 32;
    int grp  = lane >> 2, tg = lane & 3;

    int lt = lane >> 3, lr = lane & 7;
    uint32_t smb = s2u(sm);
    uint32_t aAdr = smb + (uint32_t)((wm0 + (lt & 1) * 8 + lr) * RSB + (lt >> 1) * 16);
    uint32_t bAdr = smb + (uint32_t)((wn0 + (lt >> 1) * 8 + lr) * RSB + (lt & 1) * 16)
                  + (uint32_t)((1 + role) * ATILE_B);

    int lrow = tid >> 2;
    int lq   = tid & 3;
    int tok  = g_tok[e * CAP + m0 + lrow];
    tok = min(max(tok, 0), T_TOK - 1);
    const __half* aS  = g_xch + (size_t)tok * D_DIM + lq * 8;
    const __half* b1S = g_W1h + ((size_t)e * H_DIM + n0 + lrow) * D_DIM + lq * 8;
    const __half* b2S = g_W2h + ((size_t)e * H_DIM + n0 + lrow) * D_DIM + lq * 8;
    uint32_t dst = smb + (uint32_t)(lrow * RSB + lq * 16);

#define LOAD1(k, stg) do {                                                      \
        int kc = (k) * BK;                                                      \
        uint32_t d0 = dst + (uint32_t)(stg) * STG1_B;                           \
        CPA16(d0,               aS  + kc);                                      \
        CPA16(d0 + ATILE_B,     b1S + kc);                                      \
        CPA16(d0 + 2 * ATILE_B, b2S + kc);                                      \
    } while (0)

    float acc[4][4][4];
#pragma unroll
    for (int i = 0; i < 4; i++)
#pragma unroll
        for (int j = 0; j < 4; j++)
#pragma unroll
            for (int r = 0; r < 4; r++) acc[i][j][r] = 0.f;

#define COMPUTE1(cs) do {                                                       \
        uint32_t sA = aAdr + (uint32_t)((cs) * STG1_B);                         \
        uint32_t sB = bAdr + (uint32_t)((cs) * STG1_B);                         \
        _Pragma("unroll")                                                       \
        for (int ks = 0; ks < 2; ks++) {                                        \
            uint32_t a[4][4];                                                   \
            _Pragma("unroll")                                                   \
            for (int mt = 0; mt < 4; mt++)                                      \
                LDSM_X4(a[mt], sA + (uint32_t)(mt * 16 * RSB + ks * 32));       \
            uint32_t b[2][4];                                                   \
            _Pragma("unroll")                                                   \
            for (int p = 0; p < 2; p++)                                         \
                LDSM_X4(b[p], sB + (uint32_t)(p * 16 * RSB + ks * 32));         \
            _Pragma("unroll")                                                   \
            for (int mt = 0; mt < 4; mt++)                                      \
                _Pragma("unroll")                                               \
                for (int nt = 0; nt < 4; nt++)                                  \
                    MMA_F16(acc[mt][nt], a[mt], &b[nt >> 1][(nt & 1) * 2]);     \
        }                                                                       \
    } while (0)

    LOAD1(0, 0); CPA_COMMIT();
    LOAD1(1, 1); CPA_COMMIT();
    LOAD1(2, 2); CPA_COMMIT();
    LOAD1(3, 3); CPA_COMMIT();

    int cs = 0, ls = 4;
    for (int k = 0; k < NK1; k += 2) {
        CPA_WAIT(2);
        __syncthreads();
        if (k + 4 < NK1) LOAD1(k + 4, ls);
        CPA_COMMIT();
        if (++ls == NSTG1) ls = 0;
        COMPUTE1(cs);
        if (++cs == NSTG1) cs = 0;
        if (k + 5 < NK1) LOAD1(k + 5, ls);
        CPA_COMMIT();
        if (++ls == NSTG1) ls = 0;
        COMPUTE1(cs);
        if (++cs == NSTG1) cs = 0;
    }
#undef LOAD1
#undef COMPUTE1

    // epilogue: exchange silu(gate) via smem, write fp16 Hh
    const int XS = 34;
    float* ex = (float*)sm + pos * 64 * XS;

    __syncthreads();
    if (role == 0) {
#pragma unroll
        for (int mt = 0; mt < 4; mt++)
#pragma unroll
            for (int nt = 0; nt < 4; nt++)
#pragma unroll
                for (int h = 0; h < 2; h++) {
                    int rloc = mt * 16 + h * 8 + grp;
                    int cloc = nt * 8 + 2 * tg;
                    float g0 = acc[mt][nt][2 * h + 0];
                    float g1 = acc[mt][nt][2 * h + 1];
                    float2 s;
                    s.x = g0 / (1.f + __expf(-g0));
                    s.y = g1 / (1.f + __expf(-g1));
                    *(float2*)&ex[rloc * XS + cloc] = s;
                }
    }
    __syncthreads();
    if (role == 1) {
#pragma unroll
        for (int mt = 0; mt < 4; mt++)
#pragma unroll
            for (int nt = 0; nt < 4; nt++)
#pragma unroll
                for (int h = 0; h < 2; h++) {
                    int rloc = mt * 16 + h * 8 + grp;
                    int row  = m0 + wm0 + rloc;
                    if (row < cnt) {
                        int cloc = nt * 8 + 2 * tg;
                        float2 s = *(const float2*)&ex[rloc * XS + cloc];
                        float h0 = s.x * acc[mt][nt][2 * h + 0];
                        float h1 = s.y * acc[mt][nt][2 * h + 1];
                        *(__half2*)&g_Hh[((size_t)e * CAP + row) * H_DIM +
                                         n0 + wn0 + cloc] = __floats2half2_rn(h0, h1);
                    }
                }
    }
}

// ---------------- K3: GEMM2, out[t] += wgt * (Hh @ W3[e]^T) ------------------
// 256 threads, warp tile 64x32, occ 2, 5-stage ring; atomicAdd epilogue
// (each out element receives exactly 2 commutative fp32 adds -> deterministic).
__global__ __launch_bounds__(256, 2)
void k_ffn2(float* __restrict__ out) {
    int e  = blockIdx.x >> 5;
    int m0 = (blockIdx.x & 31) * BM;
    int cnt = g_cnt[e];
    if (m0 >= cnt) return;
    int n0 = blockIdx.y * BN;

    extern __shared__ char sm[];

    int tid  = threadIdx.x;
    int wid  = tid >> 5, lane = tid & 31;
    int wm0  = (wid & 1) * 64;
    int wn0  = (wid >> 1) * 32;
    int grp  = lane >> 2, tg = lane & 3;

    int lt = lane >> 3, lr = lane & 7;
    uint32_t smb = s2u(sm);
    uint32_t aAdr = smb + (uint32_t)((wm0 + (lt & 1) * 8 + lr) * RSB + (lt >> 1) * 16);
    uint32_t bAdr = smb + (uint32_t)((wn0 + (lt >> 1) * 8 + lr) * RSB + (lt & 1) * 16);

    int lrow = tid >> 1;
    int lch  = (tid & 1) * 16;
    const __half* aS = g_Hh  + ((size_t)e * CAP + m0 + lrow) * H_DIM + lch;
    const __half* bS = g_W3h + ((size_t)e * D_DIM + n0 + lrow) * H_DIM + lch;
    uint32_t dst = smb + (uint32_t)(lrow * RSB + (tid & 1) * 32);

#define LOAD2(k, stg) do {                                                      \
        int kc = (k) * BK;                                                      \
        uint32_t d0 = dst + (uint32_t)(stg) * STG2_B;                           \
        CPA16(d0,           aS + kc); CPA16(d0 + 16,           aS + kc + 8);    \
        CPA16(d0 + ATILE_B, bS + kc); CPA16(d0 + ATILE_B + 16, bS + kc + 8);    \
    } while (0)

    float acc[4][4][4];
#pragma unroll
    for (int i = 0; i < 4; i++)
#pragma unroll
        for (int j = 0; j < 4; j++)
#pragma unroll
            for (int r = 0; r < 4; r++) acc[i][j][r] = 0.f;

#define COMPUTE2(cs) do {                                                       \
        uint32_t sA = aAdr + (uint32_t)((cs) * STG2_B);                         \
        uint32_t sB = bAdr + (uint32_t)((cs) * STG2_B + ATILE_B);               \
        _Pragma("unroll")                                                       \
        for (int ks = 0; ks < 2; ks++) {                                        \
            uint32_t a[4][4];                                                   \
            _Pragma("unroll")                                                   \
            for (int mt = 0; mt < 4; mt++)                                      \
                LDSM_X4(a[mt], sA + (uint32_t)(mt * 16 * RSB + ks * 32));       \
            uint32_t b[2][4];                                                   \
            _Pragma("unroll")                                                   \
            for (int p = 0; p < 2; p++)                                         \
                LDSM_X4(b[p], sB + (uint32_t)(p * 16 * RSB + ks * 32));         \
            _Pragma("unroll")                                                   \
            for (int mt = 0; mt < 4; mt++)                                      \
                _Pragma("unroll")                                               \
                for (int nt = 0; nt < 4; nt++)                                  \
                    MMA_F16(acc[mt][nt], a[mt], &b[nt >> 1][(nt & 1) * 2]);     \
        }                                                                       \
    } while (0)

    LOAD2(0, 0); CPA_COMMIT();
    LOAD2(1, 1); CPA_COMMIT();
    LOAD2(2, 2); CPA_COMMIT();

    int cs = 0, ls = 3;
    for (int k = 0; k < NK2; k += 2) {
        CPA_WAIT(1);
        __syncthreads();
        if (k + 3 < NK2) LOAD2(k + 3, ls);
        CPA_COMMIT();
        if (++ls == NSTG2) ls = 0;
        COMPUTE2(cs);
        if (++cs == NSTG2) cs = 0;
        if (k + 4 < NK2) LOAD2(k + 4, ls);
        CPA_COMMIT();
        if (++ls == NSTG2) ls = 0;
        COMPUTE2(cs);
        if (++cs == NSTG2) cs = 0;
    }
#undef LOAD2
#undef COMPUTE2

#pragma unroll
    for (int mt = 0; mt < 4; mt++) {
        int r0 = m0 + wm0 + mt * 16 + grp;
#pragma unroll
        for (int h = 0; h < 2; h++) {
            int row = r0 + h * 8;
            if (row < cnt) {
                float w = g_wgt[e * CAP + row];
                int t   = g_tok[e * CAP + row];
                float* op = out + (size_t)t * D_DIM;
#pragma unroll
                for (int nt = 0; nt < 4; nt++) {
                    int cc = n0 + wn0 + nt * 8 + 2 * tg;
                    atomicAdd(op + cc,     w * acc[mt][nt][2 * h + 0]);
                    atomicAdd(op + cc + 1, w * acc[mt][nt][2 * h + 1]);
                }
            }
        }
    }
}

// -----------------------------------------------------------------------------
extern "C" void kernel_launch(void* const* d_in, const int* in_sizes, int n_in,
                              void* d_out, int out_size) {
    const float* x  = (const float*)d_in[0];
    const float* Wg = (const float*)d_in[1];
    const float* W1 = (const float*)d_in[2];
    const float* W2 = (const float*)d_in[3];
    const float* W3 = (const float*)d_in[4];
    float* out = (float*)d_out;

    cudaFuncSetAttribute(k_ffn1, cudaFuncAttributeMaxDynamicSharedMemorySize, SMEM1_BYTES);
    cudaFuncSetAttribute(k_ffn2, cudaFuncAttributeMaxDynamicSharedMemorySize, SMEM2_BYTES);

    void *p_w1, *p_w2, *p_w3, *p_cnt;
    cudaGetSymbolAddress(&p_w1, g_W1h);
    cudaGetSymbolAddress(&p_w2, g_W2h);
    cudaGetSymbolAddress(&p_w3, g_W3h);
    cudaGetSymbolAddress(&p_cnt, g_cnt);

    // zero expert counters (tiny memset; must precede gate atomics)
    cudaMemsetAsync(p_cnt, 0, E_NUM * sizeof(int));

    // K1: gate (+x conversion) | out-zero | W1/W2 conversion, one launch
    k_front<<<GATE_BLKS + ZERO_BLKS + CONV12_BLKS, 256>>>(
        x, Wg, (const float4*)W1, (const float4*)W2,
        (__half2*)p_w1, (__half2*)p_w2, (float4*)out);

    // K2: ffn1 + W3 converter blocks (y == NB1, enumerated last)
    dim3 g1(E_NUM * (CAP / BM), NB1 + 1);      // (256, 23)
    k_ffn1<<<g1, 512, SMEM1_BYTES>>>((const float4*)W3, (__half2*)p_w3);

    // K3: ffn2 with fused routed accumulation into out
    dim3 g2(E_NUM * (CAP / BM), D_DIM / BN);   // (256, 8)
    k_ffn2<<<g2, 256, SMEM2_BYTES>>>(out);
}

// round 17
// speedup vs baseline: 1.0230x; 1.0230x over previous
#include <cuda_runtime.h>
#include <cuda_fp16.h>
#include <cstdint>
#include <math.h>

// ---------------- problem constants ------------------------------------------
#define T_TOK 4096
#define D_DIM 1024
#define H_DIM 2816
#define E_NUM 8
#define CAP   4096

#define BM 128
#define BN 128
#define BK 32                      // K halves per stage: 64B data/row
#define RSB 80                     // padded smem row stride in BYTES
#define ATILE_B (BM * RSB)         // 10240 bytes per 128-row tile
#define NK1 (D_DIM / BK)           // 32
#define NK2 (H_DIM / BK)           // 88
#define NSTG1 6                    // ffn1 ring depth (preload 4)
#define NSTG2 5                    // ffn2 ring depth (preload 3, occ 2)
#define NB1  (H_DIM / BN)          // 22 n-blocks in ffn1; blockIdx.y==NB1 -> W3 conv

#define STG1_B (3 * ATILE_B)                   // A + B1 + B2 = 30720
#define STG2_B (2 * ATILE_B)                   // A + B = 20480
#define SMEM1_BYTES (NSTG1 * STG1_B)           // 184320
#define SMEM2_BYTES (NSTG2 * STG2_B)           // 102400

#define N4W ((long)E_NUM * H_DIM * D_DIM / 4)  // 5767168 float4 per weight tensor
#define N4O ((long)T_TOK * D_DIM / 4)          // 1048576 float4 in out

#define GATE_BLKS 512                          // 8 tokens per 256-thread block
#define ZERO_BLKS 128                          // out-zero blocks
#define CONVW_BLKS 1024                        // converter blocks per weight tensor
#define CONV3_BLKS 256                         // W3 converter blocks in K2 (y==NB1)

// ---------------- static device scratch --------------------------------------
__device__ __half g_xch[(size_t)T_TOK * D_DIM];
__device__ __half g_W1h[(size_t)E_NUM * H_DIM * D_DIM];
__device__ __half g_W2h[(size_t)E_NUM * H_DIM * D_DIM];
__device__ __half g_W3h[(size_t)E_NUM * D_DIM * H_DIM];
__device__ __half g_Hh [(size_t)E_NUM * CAP * H_DIM];
__device__ int    g_tok[E_NUM * CAP];
__device__ float  g_wgt[E_NUM * CAP];
__device__ int    g_cnt[E_NUM];

// ---------------- helpers -----------------------------------------------------
__device__ __forceinline__ uint32_t s2u(const void* p) {
    uint32_t a;
    asm("{ .reg .u64 t; cvta.to.shared.u64 t, %1; cvt.u32.u64 %0, t; }" : "=r"(a) : "l"(p));
    return a;
}

#define CPA16(s, g) asm volatile("cp.async.cg.shared.global [%0], [%1], 16;" :: "r"(s), "l"(g))
#define CPA_COMMIT() asm volatile("cp.async.commit_group;" ::: "memory")
#define CPA_WAIT(n)  asm volatile("cp.async.wait_group %0;" :: "n"(n) : "memory")

#define LDSM_X4(r, addr)                                                          \
    asm volatile("ldmatrix.sync.aligned.m8n8.x4.shared.b16 {%0,%1,%2,%3}, [%4];"  \
        : "=r"((r)[0]), "=r"((r)[1]), "=r"((r)[2]), "=r"((r)[3]) : "r"(addr))

#define MMA_F16(d, a, b)                                                          \
    asm volatile(                                                                 \
        "mma.sync.aligned.m16n8k16.row.col.f32.f16.f16.f32 "                      \
        "{%0,%1,%2,%3},{%4,%5,%6,%7},{%8,%9},{%0,%1,%2,%3};"                      \
        : "+f"((d)[0]), "+f"((d)[1]), "+f"((d)[2]), "+f"((d)[3])                  \
        : "r"((a)[0]), "r"((a)[1]), "r"((a)[2]), "r"((a)[3]),                     \
          "r"((b)[0]), "r"((b)[1]))

__device__ __forceinline__ void conv_f4(const float4* __restrict__ s,
                                        __half2* __restrict__ d, long i) {
    float4 v = s[i];
    d[i * 2 + 0] = __floats2half2_rn(v.x, v.y);
    d[i * 2 + 1] = __floats2half2_rn(v.z, v.w);
}

// ---------------- K1: gate (+x conv) | out-zero | W1 conv | W2 conv ----------
__global__ void k_front(const float* __restrict__ x,
                        const float* __restrict__ Wg,
                        const float4* __restrict__ W1,
                        const float4* __restrict__ W2,
                        __half2* __restrict__ w1c,
                        __half2* __restrict__ w2c,
                        float4* __restrict__ out4) {
    if (blockIdx.x < GATE_BLKS) {
        // ---- gate: one warp per token; also writes fp16 x row ----
        int t = blockIdx.x * 8 + (threadIdx.x >> 5);
        int lane = threadIdx.x & 31;
        const float4* xr = (const float4*)(x + (size_t)t * D_DIM);
        float acc[E_NUM];
#pragma unroll
        for (int e = 0; e < E_NUM; e++) acc[e] = 0.f;
        for (int i = lane; i < D_DIM / 4; i += 32) {
            float4 xv = xr[i];
            uint2 u;
            __half2 h0 = __floats2half2_rn(xv.x, xv.y);
            __half2 h1 = __floats2half2_rn(xv.z, xv.w);
            u.x = *(uint32_t*)&h0; u.y = *(uint32_t*)&h1;
            *(uint2*)&g_xch[(size_t)t * D_DIM + i * 4] = u;
#pragma unroll
            for (int e = 0; e < E_NUM; e++) {
                float4 wv = ((const float4*)(Wg + (size_t)e * D_DIM))[i];
                acc[e] += xv.x * wv.x + xv.y * wv.y + xv.z * wv.z + xv.w * wv.w;
            }
        }
#pragma unroll
        for (int e = 0; e < E_NUM; e++)
#pragma unroll
            for (int o = 16; o > 0; o >>= 1)
                acc[e] += __shfl_xor_sync(0xffffffffu, acc[e], o);
        if (lane == 0) {
            int e0 = 0; float v0 = acc[0];
#pragma unroll
            for (int e = 1; e < E_NUM; e++) if (acc[e] > v0) { v0 = acc[e]; e0 = e; }
            int e1 = -1; float v1 = -INFINITY;
#pragma unroll
            for (int e = 0; e < E_NUM; e++)
                if (e != e0 && acc[e] > v1) { v1 = acc[e]; e1 = e; }
            int i0 = atomicAdd(&g_cnt[e0], 1);
            g_tok[e0 * CAP + i0] = t; g_wgt[e0 * CAP + i0] = v0;
            int i1 = atomicAdd(&g_cnt[e1], 1);
            g_tok[e1 * CAP + i1] = t; g_wgt[e1 * CAP + i1] = v1;
        }
    } else if (blockIdx.x < GATE_BLKS + ZERO_BLKS) {
        // ---- zero the fp32 output accumulator ----
        float4 z; z.x = 0.f; z.y = 0.f; z.z = 0.f; z.w = 0.f;
        const long stride = (long)ZERO_BLKS * 256;
        for (long i = (long)(blockIdx.x - GATE_BLKS) * 256 + threadIdx.x;
             i < N4O; i += stride)
            out4[i] = z;
    } else if (blockIdx.x < GATE_BLKS + ZERO_BLKS + CONVW_BLKS) {
        // ---- W1 fp32->fp16, simple grid-stride (R15-proven pattern) ----
        const long stride = (long)CONVW_BLKS * 256;
        for (long i = (long)(blockIdx.x - GATE_BLKS - ZERO_BLKS) * 256 + threadIdx.x;
             i < N4W; i += stride)
            conv_f4(W1, w1c, i);
    } else {
        // ---- W2 fp32->fp16 ----
        const long stride = (long)CONVW_BLKS * 256;
        for (long i = (long)(blockIdx.x - GATE_BLKS - ZERO_BLKS - CONVW_BLKS) * 256
                      + threadIdx.x;
             i < N4W; i += stride)
            conv_f4(W2, w2c, i);
    }
}

// ---------------- K2: GEMM1 (+W3 conversion blocks at y==NB1) ----------------
// Split-role: 512 threads = 8 positions (64x32 subtile) x 2 roles (gate/up).
// 6-stage cp.async ring, preload 4, barrier per 2 stages.
__global__ __launch_bounds__(512, 1)
void k_ffn1(const float4* __restrict__ W3, __half2* __restrict__ w3c) {
    if (blockIdx.y == NB1) {
        const long stride = (long)CONV3_BLKS * 512;
        for (long i = (long)blockIdx.x * 512 + threadIdx.x; i < N4W; i += stride)
            conv_f4(W3, w3c, i);
        return;
    }
    int e  = blockIdx.x >> 5;
    int m0 = (blockIdx.x & 31) * BM;
    int cnt = g_cnt[e];
    if (m0 >= cnt) return;
    int n0 = blockIdx.y * BN;

    extern __shared__ char sm[];

    int tid  = threadIdx.x;
    int wid  = tid >> 5, lane = tid & 31;
    int pos  = wid >> 1;
    int role = wid & 1;                // 0 = gate (W1), 1 = up (W2)
    int wm0  = (pos & 1) * 64;
    int wn0  = (pos >> 1) * 32;
    int grp  = lane >> 2, tg = lane & 3;

    int lt = lane >> 3, lr = lane & 7;
    uint32_t smb = s2u(sm);
    uint32_t aAdr = smb + (uint32_t)((wm0 + (lt & 1) * 8 + lr) * RSB + (lt >> 1) * 16);
    uint32_t bAdr = smb + (uint32_t)((wn0 + (lt >> 1) * 8 + lr) * RSB + (lt & 1) * 16)
                  + (uint32_t)((1 + role) * ATILE_B);

    int lrow = tid >> 2;
    int lq   = tid & 3;
    int tok  = g_tok[e * CAP + m0 + lrow];
    tok = min(max(tok, 0), T_TOK - 1);
    const __half* aS  = g_xch + (size_t)tok * D_DIM + lq * 8;
    const __half* b1S = g_W1h + ((size_t)e * H_DIM + n0 + lrow) * D_DIM + lq * 8;
    const __half* b2S = g_W2h + ((size_t)e * H_DIM + n0 + lrow) * D_DIM + lq * 8;
    uint32_t dst = smb + (uint32_t)(lrow * RSB + lq * 16);

#define LOAD1(k, stg) do {                                                      \
        int kc = (k) * BK;                                                      \
        uint32_t d0 = dst + (uint32_t)(stg) * STG1_B;                           \
        CPA16(d0,               aS  + kc);                                      \
        CPA16(d0 + ATILE_B,     b1S + kc);                                      \
        CPA16(d0 + 2 * ATILE_B, b2S + kc);                                      \
    } while (0)

    float acc[4][4][4];
#pragma unroll
    for (int i = 0; i < 4; i++)
#pragma unroll
        for (int j = 0; j < 4; j++)
#pragma unroll
            for (int r = 0; r < 4; r++) acc[i][j][r] = 0.f;

#define COMPUTE1(cs) do {                                                       \
        uint32_t sA = aAdr + (uint32_t)((cs) * STG1_B);                         \
        uint32_t sB = bAdr + (uint32_t)((cs) * STG1_B);                         \
        _Pragma("unroll")                                                       \
        for (int ks = 0; ks < 2; ks++) {                                        \
            uint32_t a[4][4];                                                   \
            _Pragma("unroll")                                                   \
            for (int mt = 0; mt < 4; mt++)                                      \
                LDSM_X4(a[mt], sA + (uint32_t)(mt * 16 * RSB + ks * 32));       \
            uint32_t b[2][4];                                                   \
            _Pragma("unroll")                                                   \
            for (int p = 0; p < 2; p++)                                         \
                LDSM_X4(b[p], sB + (uint32_t)(p * 16 * RSB + ks * 32));         \
            _Pragma("unroll")                                                   \
            for (int mt = 0; mt < 4; mt++)                                      \
                _Pragma("unroll")                                               \
                for (int nt = 0; nt < 4; nt++)                                  \
                    MMA_F16(acc[mt][nt], a[mt], &b[nt >> 1][(nt & 1) * 2]);     \
        }                                                                       \
    } while (0)

    LOAD1(0, 0); CPA_COMMIT();
    LOAD1(1, 1); CPA_COMMIT();
    LOAD1(2, 2); CPA_COMMIT();
    LOAD1(3, 3); CPA_COMMIT();

    int cs = 0, ls = 4;
    for (int k = 0; k < NK1; k += 2) {
        CPA_WAIT(2);
        __syncthreads();
        if (k + 4 < NK1) LOAD1(k + 4, ls);
        CPA_COMMIT();
        if (++ls == NSTG1) ls = 0;
        COMPUTE1(cs);
        if (++cs == NSTG1) cs = 0;
        if (k + 5 < NK1) LOAD1(k + 5, ls);
        CPA_COMMIT();
        if (++ls == NSTG1) ls = 0;
        COMPUTE1(cs);
        if (++cs == NSTG1) cs = 0;
    }
#undef LOAD1
#undef COMPUTE1

    // epilogue: exchange silu(gate) via smem, write fp16 Hh
    const int XS = 34;
    float* ex = (float*)sm + pos * 64 * XS;

    __syncthreads();
    if (role == 0) {
#pragma unroll
        for (int mt = 0; mt < 4; mt++)
#pragma unroll
            for (int nt = 0; nt < 4; nt++)
#pragma unroll
                for (int h = 0; h < 2; h++) {
                    int rloc = mt * 16 + h * 8 + grp;
                    int cloc = nt * 8 + 2 * tg;
                    float g0 = acc[mt][nt][2 * h + 0];
                    float g1 = acc[mt][nt][2 * h + 1];
                    float2 s;
                    s.x = g0 / (1.f + __expf(-g0));
                    s.y = g1 / (1.f + __expf(-g1));
                    *(float2*)&ex[rloc * XS + cloc] = s;
                }
    }
    __syncthreads();
    if (role == 1) {
#pragma unroll
        for (int mt = 0; mt < 4; mt++)
#pragma unroll
            for (int nt = 0; nt < 4; nt++)
#pragma unroll
                for (int h = 0; h < 2; h++) {
                    int rloc = mt * 16 + h * 8 + grp;
                    int row  = m0 + wm0 + rloc;
                    if (row < cnt) {
                        int cloc = nt * 8 + 2 * tg;
                        float2 s = *(const float2*)&ex[rloc * XS + cloc];
                        float h0 = s.x * acc[mt][nt][2 * h + 0];
                        float h1 = s.y * acc[mt][nt][2 * h + 1];
                        *(__half2*)&g_Hh[((size_t)e * CAP + row) * H_DIM +
                                         n0 + wn0 + cloc] = __floats2half2_rn(h0, h1);
                    }
                }
    }
}

// ---------------- K3: GEMM2, out[t] += wgt * (Hh @ W3[e]^T) ------------------
// 256 threads, warp tile 64x32, occ 2, 5-stage ring; atomicAdd epilogue
// (each out element receives exactly 2 commutative fp32 adds -> deterministic).
__global__ __launch_bounds__(256, 2)
void k_ffn2(float* __restrict__ out) {
    int e  = blockIdx.x >> 5;
    int m0 = (blockIdx.x & 31) * BM;
    int cnt = g_cnt[e];
    if (m0 >= cnt) return;
    int n0 = blockIdx.y * BN;

    extern __shared__ char sm[];

    int tid  = threadIdx.x;
    int wid  = tid >> 5, lane = tid & 31;
    int wm0  = (wid & 1) * 64;
    int wn0  = (wid >> 1) * 32;
    int grp  = lane >> 2, tg = lane & 3;

    int lt = lane >> 3, lr = lane & 7;
    uint32_t smb = s2u(sm);
    uint32_t aAdr = smb + (uint32_t)((wm0 + (lt & 1) * 8 + lr) * RSB + (lt >> 1) * 16);
    uint32_t bAdr = smb + (uint32_t)((wn0 + (lt >> 1) * 8 + lr) * RSB + (lt & 1) * 16);

    int lrow = tid >> 1;
    int lch  = (tid & 1) * 16;
    const __half* aS = g_Hh  + ((size_t)e * CAP + m0 + lrow) * H_DIM + lch;
    const __half* bS = g_W3h + ((size_t)e * D_DIM + n0 + lrow) * H_DIM + lch;
    uint32_t dst = smb + (uint32_t)(lrow * RSB + (tid & 1) * 32);

#define LOAD2(k, stg) do {                                                      \
        int kc = (k) * BK;                                                      \
        uint32_t d0 = dst + (uint32_t)(stg) * STG2_B;                           \
        CPA16(d0,           aS + kc); CPA16(d0 + 16,           aS + kc + 8);    \
        CPA16(d0 + ATILE_B, bS + kc); CPA16(d0 + ATILE_B + 16, bS + kc + 8);    \
    } while (0)

    float acc[4][4][4];
#pragma unroll
    for (int i = 0; i < 4; i++)
#pragma unroll
        for (int j = 0; j < 4; j++)
#pragma unroll
            for (int r = 0; r < 4; r++) acc[i][j][r] = 0.f;

#define COMPUTE2(cs) do {                                                       \
        uint32_t sA = aAdr + (uint32_t)((cs) * STG2_B);                         \
        uint32_t sB = bAdr + (uint32_t)((cs) * STG2_B + ATILE_B);               \
        _Pragma("unroll")                                                       \
        for (int ks = 0; ks < 2; ks++) {                                        \
            uint32_t a[4][4];                                                   \
            _Pragma("unroll")                                                   \
            for (int mt = 0; mt < 4; mt++)                                      \
                LDSM_X4(a[mt], sA + (uint32_t)(mt * 16 * RSB + ks * 32));       \
            uint32_t b[2][4];                                                   \
            _Pragma("unroll")                                                   \
            for (int p = 0; p < 2; p++)                                         \
                LDSM_X4(b[p], sB + (uint32_t)(p * 16 * RSB + ks * 32));         \
            _Pragma("unroll")                                                   \
            for (int mt = 0; mt < 4; mt++)                                      \
                _Pragma("unroll")                                               \
                for (int nt = 0; nt < 4; nt++)                                  \
                    MMA_F16(acc[mt][nt], a[mt], &b[nt >> 1][(nt & 1) * 2]);     \
        }                                                                       \
    } while (0)

    LOAD2(0, 0); CPA_COMMIT();
    LOAD2(1, 1); CPA_COMMIT();
    LOAD2(2, 2); CPA_COMMIT();

    int cs = 0, ls = 3;
    for (int k = 0; k < NK2; k += 2) {
        CPA_WAIT(1);
        __syncthreads();
        if (k + 3 < NK2) LOAD2(k + 3, ls);
        CPA_COMMIT();
        if (++ls == NSTG2) ls = 0;
        COMPUTE2(cs);
        if (++cs == NSTG2) cs = 0;
        if (k + 4 < NK2) LOAD2(k + 4, ls);
        CPA_COMMIT();
        if (++ls == NSTG2) ls = 0;
        COMPUTE2(cs);
        if (++cs == NSTG2) cs = 0;
    }
#undef LOAD2
#undef COMPUTE2

#pragma unroll
    for (int mt = 0; mt < 4; mt++) {
        int r0 = m0 + wm0 + mt * 16 + grp;
#pragma unroll
        for (int h = 0; h < 2; h++) {
            int row = r0 + h * 8;
            if (row < cnt) {
                float w = g_wgt[e * CAP + row];
                int t   = g_tok[e * CAP + row];
                float* op = out + (size_t)t * D_DIM;
#pragma unroll
                for (int nt = 0; nt < 4; nt++) {
                    int cc = n0 + wn0 + nt * 8 + 2 * tg;
                    atomicAdd(op + cc,     w * acc[mt][nt][2 * h + 0]);
                    atomicAdd(op + cc + 1, w * acc[mt][nt][2 * h + 1]);
                }
            }
        }
    }
}

// -----------------------------------------------------------------------------
extern "C" void kernel_launch(void* const* d_in, const int* in_sizes, int n_in,
                              void* d_out, int out_size) {
    const float* x  = (const float*)d_in[0];
    const float* Wg = (const float*)d_in[1];
    const float* W1 = (const float*)d_in[2];
    const float* W2 = (const float*)d_in[3];
    const float* W3 = (const float*)d_in[4];
    float* out = (float*)d_out;

    cudaFuncSetAttribute(k_ffn1, cudaFuncAttributeMaxDynamicSharedMemorySize, SMEM1_BYTES);
    cudaFuncSetAttribute(k_ffn2, cudaFuncAttributeMaxDynamicSharedMemorySize, SMEM2_BYTES);

    void *p_w1, *p_w2, *p_w3, *p_cnt;
    cudaGetSymbolAddress(&p_w1, g_W1h);
    cudaGetSymbolAddress(&p_w2, g_W2h);
    cudaGetSymbolAddress(&p_w3, g_W3h);
    cudaGetSymbolAddress(&p_cnt, g_cnt);

    // zero expert counters (tiny memset; must precede gate atomics)
    cudaMemsetAsync(p_cnt, 0, E_NUM * sizeof(int));

    // K1: gate (+x conversion) | out-zero | W1 conv | W2 conv, one launch
    k_front<<<GATE_BLKS + ZERO_BLKS + 2 * CONVW_BLKS, 256>>>(
        x, Wg, (const float4*)W1, (const float4*)W2,
        (__half2*)p_w1, (__half2*)p_w2, (float4*)out);

    // K2: ffn1 + W3 converter blocks (y == NB1, enumerated last)
    dim3 g1(E_NUM * (CAP / BM), NB1 + 1);      // (256, 23)
    k_ffn1<<<g1, 512, SMEM1_BYTES>>>((const float4*)W3, (__half2*)p_w3);

    // K3: ffn2 with fused routed accumulation into out
    dim3 g2(E_NUM * (CAP / BM), D_DIM / BN);   // (256, 8)
    k_ffn2<<<g2, 256, SMEM2_BYTES>>>(out);
}